// round 17
// baseline (speedup 1.0000x reference)
#include <cuda_runtime.h>
#include <cuda_fp16.h>
#include <cstdint>

// ---------------------------------------------------------------------------
// Round 17: R16 (fp16 W+A, 1 MMA/chunk, 32 rows/warp, TPB=256 x 2 CTAs)
// with the two tile epilogues INTERLEAVED: 8 parallel LN reduction chains,
// shared param loads, B2 fragments loaded once per k2 for both tiles,
// 8 independent layer-2 accumulator streams.
// ---------------------------------------------------------------------------

typedef unsigned long long u64;

constexpr int TPB  = 256;
constexpr int ROWS = 256;     // 8 warps x 32 rows

// smem word offsets
constexpr int B1F = 0;        // W1 frags: 32 groups * 132 words = 4224
constexpr int B2F = 4224;     // W2 frags: 16 groups * 72 words  = 1152
constexpr int PAR = 5376;
constexpr int P_B1 = 0, P_GM = 64, P_BT = 128, P_B2 = 192, P_WG = 224,
              P_BG = 288, P_BR = 290, P_SG = 304, P_WR = 448; // end 704
constexpr int SMEM_BYTES = (5376 + 704) * 4;   // 24320

static __device__ __forceinline__ void mma_f16(float d[4], const uint32_t a[4],
                                               uint32_t b0, uint32_t b1) {
    asm volatile(
        "mma.sync.aligned.m16n8k16.row.col.f32.f16.f16.f32 "
        "{%0,%1,%2,%3}, {%4,%5,%6,%7}, {%8,%9}, {%0,%1,%2,%3};"
        : "+f"(d[0]), "+f"(d[1]), "+f"(d[2]), "+f"(d[3])
        : "r"(a[0]), "r"(a[1]), "r"(a[2]), "r"(a[3]), "r"(b0), "r"(b1));
}

static __device__ __forceinline__ u64 pk2(float x, float y) {
    u64 r; asm("mov.b64 %0, {%1, %2};" : "=l"(r) : "f"(x), "f"(y)); return r;
}
static __device__ __forceinline__ float2 unpk(u64 v) {
    float2 f; asm("mov.b64 {%0, %1}, %2;" : "=f"(f.x), "=f"(f.y) : "l"(v)); return f;
}
#define FMA2(d, a, b, c) asm("fma.rn.f32x2 %0, %1, %2, %3;" : "=l"(d) : "l"(a), "l"(b), "l"(c))
#define MUL2(d, a, b)    asm("mul.rn.f32x2 %0, %1, %2;"     : "=l"(d) : "l"(a), "l"(b))
#define ADD2(d, a, b)    asm("add.rn.f32x2 %0, %1, %2;"     : "=l"(d) : "l"(a), "l"(b))

static __device__ __forceinline__ uint32_t packh2(float a, float b) {
    __half2 h2 = __floats2half2_rn(a, b);
    return *reinterpret_cast<uint32_t*>(&h2);
}
static __device__ __forceinline__ uint32_t packh2p(u64 v2) {
    float2 f = unpk(v2);
    return packh2(f.x, f.y);
}

static __device__ __forceinline__ float rcp_fast(float x) {
    float r; asm("rcp.approx.f32 %0, %1;" : "=f"(r) : "f"(x)); return r;
}
static __device__ __forceinline__ float ex2_fast(float x) {
    float r; asm("ex2.approx.f32 %0, %1;" : "=f"(r) : "f"(x)); return r;
}

// packed branchless erf GELU (A&S 7.1.25, |erf err| <= 2.5e-5)
static __device__ __forceinline__ u64 gelu2(u64 v2) {
    u64 av;
    asm("and.b64 %0, %1, %2;" : "=l"(av) : "l"(v2), "l"(0x7FFFFFFF7FFFFFFFull));
    const float IS2 = 0.70710678118654752440f;
    u64 x2;  MUL2(x2, av, pk2(IS2, IS2));
    u64 u;   FMA2(u, x2, pk2(0.47047f, 0.47047f), pk2(1.f, 1.f));
    float2 uf = unpk(u);
    u64 t2 = pk2(rcp_fast(uf.x), rcp_fast(uf.y));
    u64 p;
    FMA2(p, t2, pk2(0.7478556f, 0.7478556f), pk2(-0.0958798f, -0.0958798f));
    FMA2(p, p, t2, pk2(0.3480242f, 0.3480242f));
    MUL2(p, p, t2);
    u64 xx;  MUL2(xx, x2, x2);
    u64 ea;  MUL2(ea, xx, pk2(-1.4426950408889634f, -1.4426950408889634f));
    float2 ef = unpk(ea);
    u64 pe;  MUL2(pe, p, pk2(ex2_fast(ef.x), ex2_fast(ef.y)));
    u64 erf2; FMA2(erf2, pe, pk2(-1.f, -1.f), pk2(1.f, 1.f));
    u64 habs; MUL2(habs, x2, pk2(IS2, IS2));
    u64 hv;   MUL2(hv, v2, pk2(0.5f, 0.5f));
    u64 res;  FMA2(res, habs, erf2, hv);
    return res;
}

__global__ __launch_bounds__(TPB, 2)
void nml_mma_kernel(
    const float* __restrict__ x, const int* __restrict__ regime,
    const float* __restrict__ W1, const float* __restrict__ b1,
    const float* __restrict__ gamma, const float* __restrict__ beta,
    const float* __restrict__ W2, const float* __restrict__ b2,
    const float* __restrict__ Wg, const float* __restrict__ bg,
    const float* __restrict__ Wr, const float* __restrict__ br,
    const float* __restrict__ emb, const float* __restrict__ log_temp,
    float* __restrict__ out, int B)
{
    extern __shared__ float smem[];
    uint32_t* smu = reinterpret_cast<uint32_t*>(smem);
    float* par = smem + PAR;

    const int tid = threadIdx.x;

    // ---- W1 -> fp16 B frags, LDS.128 layout (stride 132 words) -------------
    for (int i = tid; i < 4096; i += TPB) {
        int n = i >> 6, cp = i & 63;
        int ks = cp >> 3, r = cp & 7, sq = r >> 1, j = r & 1;
        int qq = n & 7, nt = n >> 3;
        float2 wv = *reinterpret_cast<const float2*>(W1 + n * 128 + cp * 2);
        smu[B1F + (ks * 4 + sq) * 132 + (qq * 8 + nt) * 2 + j] =
            packh2(wv.x, wv.y);
    }
    // ---- W2 -> fp16 (LDS.64 layout, stride 36 pairs) ------------------------
    for (int i = tid; i < 1024; i += TPB) {
        int n = i >> 5, kpg = i & 31;
        int k2 = kpg >> 3, r = kpg & 7, sq = r & 3, j = r >> 2;
        float2 wv = *reinterpret_cast<const float2*>(W2 + n * 64 + kpg * 2);
        smu[B2F + ((k2 * 4 + sq) * 36 + n) * 2 + j] = packh2(wv.x, wv.y);
    }
    // ---- params --------------------------------------------------------------
    if (tid < 64) {
        par[P_B1 + tid] = b1[tid];
        par[P_GM + tid] = gamma[tid];
        par[P_BT + tid] = beta[tid];
    }
    if (tid < 32) {
        par[P_B2 + tid] = b2[tid];
        par[P_WG + 2 * tid]     = Wg[tid];
        par[P_WG + 2 * tid + 1] = Wg[32 + tid];
    }
    if (tid < 2)  par[P_BG + tid] = 0.7f * bg[tid];
    if (tid < 8)  par[P_BR + tid] = 0.3f * br[tid];
    if (tid < 128) {
        int rr = tid >> 5, c = tid & 31;
        par[P_SG + rr * 36 + c] = 0.5f + 0.2f / (1.0f + expf(-emb[tid]));
    }
    {
        int rr = tid >> 6, rest = tid & 63, ch = rest >> 1, sel = rest & 1;
        par[P_WR + rr * 64 + ch * 2 + sel] = Wr[rr * 64 + sel * 32 + ch];
    }
    __syncthreads();

    const int wid  = tid >> 5;
    const int lane = tid & 31;
    const int q    = lane >> 2;
    const int s4   = lane & 3;
    const int q4   = q * 4;
    const int warpRow = blockIdx.x * ROWS + wid * 32;
    const int Bm1 = B - 1;

    // ---- regime prefetch ------------------------------------------------------
    int rrl[2], rrh[2];
#pragma unroll
    for (int t = 0; t < 2; t++) {
        int glo = warpRow + t * 16 + q;
        int ghi = glo + 8;
        rrl[t] = regime[glo > Bm1 ? Bm1 : glo];
        rrh[t] = regime[ghi > Bm1 ? Bm1 : ghi];
    }

    // ======================= layer 1: D1 = X @ W1^T ==========================
    float d1[2][8][4];
#pragma unroll
    for (int t = 0; t < 2; t++)
#pragma unroll
        for (int nt = 0; nt < 8; nt++)
#pragma unroll
            for (int j = 0; j < 4; j++) d1[t][nt][j] = 0.f;

#pragma unroll 2
    for (int ks = 0; ks < 8; ks++) {
        uint32_t A[2][4];
#pragma unroll
        for (int t = 0; t < 2; t++) {
            int rlo = warpRow + t * 16 + q;
            int rhi = rlo + 8;
            if (rlo > Bm1) rlo = Bm1;
            if (rhi > Bm1) rhi = Bm1;
            float4 vlo = *reinterpret_cast<const float4*>(
                x + rlo * 128 + ks * 16 + s4 * 4);
            float4 vhi = *reinterpret_cast<const float4*>(
                x + rhi * 128 + ks * 16 + s4 * 4);
            A[t][0] = packh2(vlo.x, vlo.y);
            A[t][1] = packh2(vhi.x, vhi.y);
            A[t][2] = packh2(vlo.z, vlo.w);
            A[t][3] = packh2(vhi.z, vhi.w);
        }
        const uint4* bp = reinterpret_cast<const uint4*>(
            smu + B1F + (ks * 4 + s4) * 132);
#pragma unroll
        for (int b = 0; b < 4; b++) {
            uint4 h4 = bp[q4 + b];
            int n0 = 2 * b, n1 = 2 * b + 1;
            mma_f16(d1[0][n0], A[0], h4.x, h4.y);
            mma_f16(d1[1][n0], A[1], h4.x, h4.y);
            mma_f16(d1[0][n1], A[0], h4.z, h4.w);
            mma_f16(d1[1][n1], A[1], h4.z, h4.w);
        }
    }

    // ======================= interleaved epilogue (both tiles) ================
    float temp = expf(log_temp[0]);
    temp = fminf(fmaxf(temp, 0.5f), 5.0f);
    const float it = 1.0f / temp;

    const u64* b1v = reinterpret_cast<const u64*>(par + P_B1);
    const u64* gmv = reinterpret_cast<const u64*>(par + P_GM);
    const u64* btv = reinterpret_cast<const u64*>(par + P_BT);
    const u64* b2v = reinterpret_cast<const u64*>(par + P_B2);
    const u64* wgv = reinterpret_cast<const u64*>(par + P_WG);

    // ---- bias + one-pass sum/sumsq, both tiles (params loaded once) -----------
    u64 plo[2][8], phi[2][8];
    u64 sacc[2][2], qacc[2][2];   // [tile][lo/hi]
#pragma unroll
    for (int t = 0; t < 2; t++)
#pragma unroll
        for (int hv = 0; hv < 2; hv++) { sacc[t][hv] = 0ull; qacc[t][hv] = 0ull; }

#pragma unroll
    for (int nt = 0; nt < 8; nt++) {
        u64 bp = b1v[nt * 4 + s4];
#pragma unroll
        for (int t = 0; t < 2; t++) {
            u64 a = pk2(d1[t][nt][0], d1[t][nt][1]);
            u64 b = pk2(d1[t][nt][2], d1[t][nt][3]);
            ADD2(plo[t][nt], a, bp);
            ADD2(phi[t][nt], b, bp);
            ADD2(sacc[t][0], sacc[t][0], plo[t][nt]);
            FMA2(qacc[t][0], plo[t][nt], plo[t][nt], qacc[t][0]);
            ADD2(sacc[t][1], sacc[t][1], phi[t][nt]);
            FMA2(qacc[t][1], phi[t][nt], phi[t][nt], qacc[t][1]);
        }
    }
    // 8 independent shuffle chains
    float sred[8];
#pragma unroll
    for (int t = 0; t < 2; t++)
#pragma unroll
        for (int hv = 0; hv < 2; hv++) {
            float2 fs = unpk(sacc[t][hv]);
            float2 fq = unpk(qacc[t][hv]);
            sred[t * 2 + hv]     = fs.x + fs.y;
            sred[4 + t * 2 + hv] = fq.x + fq.y;
        }
#pragma unroll
    for (int d = 1; d <= 2; d <<= 1)
#pragma unroll
        for (int i = 0; i < 8; i++)
            sred[i] += __shfl_xor_sync(0xffffffffu, sred[i], d);

    u64 r2[2][2], nm[2][2];
#pragma unroll
    for (int t = 0; t < 2; t++)
#pragma unroll
        for (int hv = 0; hv < 2; hv++) {
            float mu  = sred[t * 2 + hv] * (1.0f / 64.0f);
            float var = sred[4 + t * 2 + hv] * (1.0f / 64.0f) - mu * mu;
            float rs  = rsqrtf(var + 1e-5f);
            r2[t][hv] = pk2(rs, rs);
            nm[t][hv] = pk2(-mu, -mu);
        }

    // ---- scale + GELU, both tiles (params loaded once) -------------------------
#pragma unroll
    for (int nt = 0; nt < 8; nt++) {
        u64 gm = gmv[nt * 4 + s4], bt = btv[nt * 4 + s4];
#pragma unroll
        for (int t = 0; t < 2; t++) {
            u64 grl; MUL2(grl, gm, r2[t][0]);
            u64 grh; MUL2(grh, gm, r2[t][1]);
            u64 btl; FMA2(btl, grl, nm[t][0], bt);
            u64 bth; FMA2(bth, grh, nm[t][1], bt);
            FMA2(plo[t][nt], plo[t][nt], grl, btl);
            FMA2(phi[t][nt], phi[t][nt], grh, bth);
            plo[t][nt] = gelu2(plo[t][nt]);
            phi[t][nt] = gelu2(phi[t][nt]);
        }
    }

    // ---- layer 2: B2 frags loaded once per k2, both tiles' MMAs ----------------
    float d2[2][4][4];
#pragma unroll
    for (int t = 0; t < 2; t++)
#pragma unroll
        for (int nt = 0; nt < 4; nt++)
#pragma unroll
            for (int j = 0; j < 4; j++) d2[t][nt][j] = 0.f;

#pragma unroll
    for (int k2 = 0; k2 < 4; k2++) {
        uint32_t A2[2][4];
#pragma unroll
        for (int t = 0; t < 2; t++) {
            A2[t][0] = packh2p(plo[t][2 * k2]);
            A2[t][1] = packh2p(phi[t][2 * k2]);
            A2[t][2] = packh2p(plo[t][2 * k2 + 1]);
            A2[t][3] = packh2p(phi[t][2 * k2 + 1]);
        }
        const uint2* bp2 = reinterpret_cast<const uint2*>(
            smu + B2F + ((k2 * 4 + s4) * 36 + q) * 2);
        uint2 bh[4];
#pragma unroll
        for (int nt = 0; nt < 4; nt++) bh[nt] = bp2[nt * 8];
#pragma unroll
        for (int nt = 0; nt < 4; nt++) {
            mma_f16(d2[0][nt], A2[0], bh[nt].x, bh[nt].y);
            mma_f16(d2[1][nt], A2[1], bh[nt].x, bh[nt].y);
        }
    }

    // ---- bias + GELU on layer-2 outputs, both tiles ------------------------------
    u64 qlo[2][4], qhi2[2][4];
#pragma unroll
    for (int nt = 0; nt < 4; nt++) {
        u64 bp = b2v[nt * 4 + s4];
#pragma unroll
        for (int t = 0; t < 2; t++) {
            u64 a = pk2(d2[t][nt][0], d2[t][nt][1]);
            u64 b = pk2(d2[t][nt][2], d2[t][nt][3]);
            ADD2(a, a, bp);
            ADD2(b, b, bp);
            qlo[t][nt]  = gelu2(a);
            qhi2[t][nt] = gelu2(b);
        }
    }

    // ---- merged heads, both tiles interleaved -------------------------------------
    u64 ca2[2][2] = {{0ull, 0ull}, {0ull, 0ull}};   // [tile][lo/hi]
    u64 cr2[2][2] = {{0ull, 0ull}, {0ull, 0ull}};
#pragma unroll
    for (int nt = 0; nt < 4; nt++) {
        int ch = nt * 8 + s4 * 2;
        u64 wg0 = wgv[ch], wg1 = wgv[ch + 1];
#pragma unroll
        for (int t = 0; t < 2; t++) {
            float2 h2  = unpk(qlo[t][nt]);
            float2 k2v = unpk(qhi2[t][nt]);
            float2 sl2 = *reinterpret_cast<const float2*>(par + P_SG + rrl[t] * 36 + ch);
            float2 sh2 = *reinterpret_cast<const float2*>(par + P_SG + rrh[t] * 36 + ch);
            const u64* wrl = reinterpret_cast<const u64*>(par + P_WR + rrl[t] * 64);
            const u64* wrh = reinterpret_cast<const u64*>(par + P_WR + rrh[t] * 64);
            float e0 = h2.x * sl2.x,  e1 = h2.y * sl2.y;
            float f0 = k2v.x * sh2.x, f1 = k2v.y * sh2.y;
            FMA2(ca2[t][0], pk2(e0, e0), wg0, ca2[t][0]);
            FMA2(ca2[t][0], pk2(e1, e1), wg1, ca2[t][0]);
            FMA2(cr2[t][0], pk2(h2.x, h2.x), wrl[ch],     cr2[t][0]);
            FMA2(cr2[t][0], pk2(h2.y, h2.y), wrl[ch + 1], cr2[t][0]);
            FMA2(ca2[t][1], pk2(f0, f0), wg0, ca2[t][1]);
            FMA2(ca2[t][1], pk2(f1, f1), wg1, ca2[t][1]);
            FMA2(cr2[t][1], pk2(k2v.x, k2v.x), wrh[ch],     cr2[t][1]);
            FMA2(cr2[t][1], pk2(k2v.y, k2v.y), wrh[ch + 1], cr2[t][1]);
        }
    }
    // 16 independent shuffle chains
    float hred[16];
#pragma unroll
    for (int t = 0; t < 2; t++)
#pragma unroll
        for (int hv = 0; hv < 2; hv++) {
            float2 ca = unpk(ca2[t][hv]);
            float2 cr = unpk(cr2[t][hv]);
            hred[(t * 2 + hv) * 4 + 0] = ca.x;
            hred[(t * 2 + hv) * 4 + 1] = ca.y;
            hred[(t * 2 + hv) * 4 + 2] = cr.x;
            hred[(t * 2 + hv) * 4 + 3] = cr.y;
        }
#pragma unroll
    for (int d = 1; d <= 2; d <<= 1)
#pragma unroll
        for (int i = 0; i < 16; i++)
            hred[i] += __shfl_xor_sync(0xffffffffu, hred[i], d);

    if (s4 == 0) {
        const float bg0 = par[P_BG], bg1 = par[P_BG + 1];
#pragma unroll
        for (int t = 0; t < 2; t++) {
            int growlo = warpRow + t * 16 + q;
            int growhi = growlo + 8;
            if (growlo < B) {
                const float* h = hred + (t * 2 + 0) * 4;
                float2 o;
                o.x = (h[0] + 0.3f * h[2] + bg0 + par[P_BR + rrl[t] * 2]) * it;
                o.y = (h[1] + 0.3f * h[3] + bg1 + par[P_BR + rrl[t] * 2 + 1]) * it;
                reinterpret_cast<float2*>(out)[growlo] = o;
            }
            if (growhi < B) {
                const float* h = hred + (t * 2 + 1) * 4;
                float2 o;
                o.x = (h[0] + 0.3f * h[2] + bg0 + par[P_BR + rrh[t] * 2]) * it;
                o.y = (h[1] + 0.3f * h[3] + bg1 + par[P_BR + rrh[t] * 2 + 1]) * it;
                reinterpret_cast<float2*>(out)[growhi] = o;
            }
        }
    }
}

extern "C" void kernel_launch(void* const* d_in, const int* in_sizes, int n_in,
                              void* d_out, int out_size)
{
    const float* x        = (const float*)d_in[0];
    const int*   regime   = (const int*)  d_in[1];
    const float* W1       = (const float*)d_in[2];
    const float* b1       = (const float*)d_in[3];
    const float* gamma    = (const float*)d_in[4];
    const float* beta     = (const float*)d_in[5];
    const float* W2       = (const float*)d_in[6];
    const float* b2       = (const float*)d_in[7];
    const float* Wg       = (const float*)d_in[8];
    const float* bg       = (const float*)d_in[9];
    const float* Wr       = (const float*)d_in[10];
    const float* br       = (const float*)d_in[11];
    const float* emb      = (const float*)d_in[12];
    const float* log_temp = (const float*)d_in[13];
    float* out = (float*)d_out;

    const int B = in_sizes[1];
    const int grid = (B + ROWS - 1) / ROWS;

    cudaFuncSetAttribute(nml_mma_kernel,
                         cudaFuncAttributeMaxDynamicSharedMemorySize, SMEM_BYTES);
    nml_mma_kernel<<<grid, TPB, SMEM_BYTES>>>(x, regime, W1, b1, gamma, beta,
                                              W2, b2, Wg, bg, Wr, br, emb,
                                              log_temp, out, B);
}